// round 5
// baseline (speedup 1.0000x reference)
#include <cuda_runtime.h>
#include <math.h>

#define B 4
#define C 256
#define H 128
#define W 128
#define S (H*W)          // 16384
#define NSCALE 4
#define DKC 64           // channels per scale

// ---------------- static scratch (no allocations allowed) ----------------
__device__ float g_q[B*C*S];         // 64MB
__device__ float g_k[B*C*S];
__device__ float g_v[B*C*S];
__device__ float g_att[B*C*S];
__device__ float g_qt[B*1048576];    // 16MB (token layout, reused per scale)
__device__ float g_kt[B*1048576];
__device__ float g_vt[B*1048576];
__device__ float g_ot[B*1048576];
__device__ float g_sc[(long)B*4096*4096];  // 256MB score scratch (max = scale 0)
__device__ float g_wt[C*C*9];        // transposed conv weights [256][2304]
__device__ float g_mean[C];
__device__ float g_var[C];

// =====================================================================
// 128x128x8 double-buffered fp32 GEMM, 256 threads, 8x8 micro-tiles.
// C[bz][m][n] = alpha * sum_k A[m][k]*B(k,n) (+ bias[m])
// A row-major [M,K]. BT=false: B row-major [K,N]; BT=true: B row-major [N,K].
// Requires M%128==0, N%128==0, K%8==0.
// =====================================================================
#define AST 132   // smem row stride (floats); 132*4B is 16B aligned, kills conflicts

template<bool BT>
__global__ __launch_bounds__(256)
void gemm128(const float* __restrict__ A, long sA,
             const float* __restrict__ Bm, long sB,
             float* __restrict__ Cm, long sC,
             const float* __restrict__ bias,
             int M, int N, int K, float alpha)
{
    const int bz = blockIdx.z;
    A  += bz * sA;
    Bm += bz * sB;
    Cm += bz * sC;
    const int m0 = blockIdx.y * 128;
    const int n0 = blockIdx.x * 128;

    __shared__ float As[2][8 * AST];
    __shared__ float Bs[2][8 * AST];

    const int tid = threadIdx.x;
    const int tx = tid & 15, ty = tid >> 4;

    // A loading: one float4 along K per thread
    const int am = tid >> 1;            // 0..127 (m within tile)
    const int ak = (tid & 1) * 4;       // 0 or 4 (k within tile)
    const float* Aptr = A + (long)(m0 + am) * K + ak;

    // B loading
    const int bk = tid >> 5;            // 0..7  (BT=false: k row)
    const int bn = (tid & 31) * 4;      // 0..124 (BT=false: n col)
    const float* Bptr = BT ? (Bm + (long)(n0 + am) * K + ak)
                           : (Bm + (long)bk * N + n0 + bn);

    float4 pa = *(const float4*)Aptr;
    float4 pb = *(const float4*)Bptr;

    // store tile 0
    {
        float* as = As[0];
        as[(ak + 0) * AST + am] = pa.x;
        as[(ak + 1) * AST + am] = pa.y;
        as[(ak + 2) * AST + am] = pa.z;
        as[(ak + 3) * AST + am] = pa.w;
        float* bs = Bs[0];
        if (BT) {
            bs[(ak + 0) * AST + am] = pb.x;
            bs[(ak + 1) * AST + am] = pb.y;
            bs[(ak + 2) * AST + am] = pb.z;
            bs[(ak + 3) * AST + am] = pb.w;
        } else {
            *(float4*)&bs[bk * AST + bn] = pb;
        }
    }
    __syncthreads();

    float acc[8][8] = {};
    const int nk = K >> 3;

    for (int it = 0; it < nk; it++) {
        const int buf = it & 1;
        if (it + 1 < nk) {
            pa = *(const float4*)(Aptr + (it + 1) * 8);
            pb = BT ? *(const float4*)(Bptr + (it + 1) * 8)
                    : *(const float4*)(Bptr + (long)(it + 1) * 8 * N);
        }
        const float* as = As[buf];
        const float* bs = Bs[buf];
        #pragma unroll
        for (int kk = 0; kk < 8; kk++) {
            float4 a0 = *(const float4*)&as[kk * AST + ty * 4];
            float4 a1 = *(const float4*)&as[kk * AST + 64 + ty * 4];
            float4 b0 = *(const float4*)&bs[kk * AST + tx * 4];
            float4 b1 = *(const float4*)&bs[kk * AST + 64 + tx * 4];
            float a[8] = {a0.x, a0.y, a0.z, a0.w, a1.x, a1.y, a1.z, a1.w};
            float b[8] = {b0.x, b0.y, b0.z, b0.w, b1.x, b1.y, b1.z, b1.w};
            #pragma unroll
            for (int i = 0; i < 8; i++)
                #pragma unroll
                for (int j = 0; j < 8; j++)
                    acc[i][j] = fmaf(a[i], b[j], acc[i][j]);
        }
        if (it + 1 < nk) {
            const int nb = buf ^ 1;
            float* as2 = As[nb];
            as2[(ak + 0) * AST + am] = pa.x;
            as2[(ak + 1) * AST + am] = pa.y;
            as2[(ak + 2) * AST + am] = pa.z;
            as2[(ak + 3) * AST + am] = pa.w;
            float* bs2 = Bs[nb];
            if (BT) {
                bs2[(ak + 0) * AST + am] = pb.x;
                bs2[(ak + 1) * AST + am] = pb.y;
                bs2[(ak + 2) * AST + am] = pb.z;
                bs2[(ak + 3) * AST + am] = pb.w;
            } else {
                *(float4*)&bs2[bk * AST + bn] = pb;
            }
        }
        __syncthreads();
    }

    #pragma unroll
    for (int i = 0; i < 8; i++) {
        const int m = m0 + ty * 4 + (i < 4 ? i : 60 + i);
        const float bb = bias ? bias[m] : 0.0f;
        float4 o0, o1;
        o0.x = acc[i][0] * alpha + bb; o0.y = acc[i][1] * alpha + bb;
        o0.z = acc[i][2] * alpha + bb; o0.w = acc[i][3] * alpha + bb;
        o1.x = acc[i][4] * alpha + bb; o1.y = acc[i][5] * alpha + bb;
        o1.z = acc[i][6] * alpha + bb; o1.w = acc[i][7] * alpha + bb;
        *(float4*)(Cm + (long)m * N + n0 + tx * 4)      = o0;
        *(float4*)(Cm + (long)m * N + n0 + 64 + tx * 4) = o1;
    }
}

// =====================================================================
// Conv3x3 as implicit GEMM: z[b][o][y][x] = bias[o] + sum_{dy,dx,c}
//   Wt[o][(dy*3+dx)*256+c] * att[b][c][y+dy-1][x+dx-1]
// M=256 (o), N=16384 (y*128+x), K=2304. One N-tile (128) == one image row.
// =====================================================================
__global__ __launch_bounds__(256)
void conv_gemm(const float* __restrict__ Wt, const float* __restrict__ in,
               const float* __restrict__ bo, float* __restrict__ z)
{
    const int bz = blockIdx.z;
    const int ybase = blockIdx.x;          // N-tile == row y
    const int m0 = blockIdx.y * 128;
    in += (long)bz * C * S;
    z  += (long)bz * C * S;

    __shared__ float As[2][8 * AST];
    __shared__ float Bs[2][8 * AST];

    const int tid = threadIdx.x;
    const int tx = tid & 15, ty = tid >> 4;

    const int am = tid >> 1;
    const int ak = (tid & 1) * 4;
    const int K = 2304;
    const float* Aptr = Wt + (long)(m0 + am) * K + ak;

    const int bk = tid >> 5;               // k row within 8-tile
    const int bn = (tid & 31) * 4;         // x base

    // guarded shifted-row B load for k-tile `it`
    auto loadB = [&](int it) -> float4 {
        const int k = it * 8 + bk;
        const int dydx = k >> 8;           // k / 256
        const int c = k & 255;
        const int dy = dydx / 3, dx = dydx % 3;
        const int y2 = ybase + dy - 1;
        float4 r = {0.f, 0.f, 0.f, 0.f};
        if ((unsigned)y2 < H) {
            const float* row = in + (long)c * S + y2 * W;
            const int x2 = bn + dx - 1;
            if ((unsigned)(x2 + 0) < W) r.x = row[x2 + 0];
            if ((unsigned)(x2 + 1) < W) r.y = row[x2 + 1];
            if ((unsigned)(x2 + 2) < W) r.z = row[x2 + 2];
            if ((unsigned)(x2 + 3) < W) r.w = row[x2 + 3];
        }
        return r;
    };

    float4 pa = *(const float4*)Aptr;
    float4 pb = loadB(0);
    {
        float* as = As[0];
        as[(ak + 0) * AST + am] = pa.x;
        as[(ak + 1) * AST + am] = pa.y;
        as[(ak + 2) * AST + am] = pa.z;
        as[(ak + 3) * AST + am] = pa.w;
        *(float4*)&Bs[0][bk * AST + bn] = pb;
    }
    __syncthreads();

    float acc[8][8] = {};
    const int nk = K >> 3;   // 288

    for (int it = 0; it < nk; it++) {
        const int buf = it & 1;
        if (it + 1 < nk) {
            pa = *(const float4*)(Aptr + (it + 1) * 8);
            pb = loadB(it + 1);
        }
        const float* as = As[buf];
        const float* bs = Bs[buf];
        #pragma unroll
        for (int kk = 0; kk < 8; kk++) {
            float4 a0 = *(const float4*)&as[kk * AST + ty * 4];
            float4 a1 = *(const float4*)&as[kk * AST + 64 + ty * 4];
            float4 b0 = *(const float4*)&bs[kk * AST + tx * 4];
            float4 b1 = *(const float4*)&bs[kk * AST + 64 + tx * 4];
            float a[8] = {a0.x, a0.y, a0.z, a0.w, a1.x, a1.y, a1.z, a1.w};
            float b[8] = {b0.x, b0.y, b0.z, b0.w, b1.x, b1.y, b1.z, b1.w};
            #pragma unroll
            for (int i = 0; i < 8; i++)
                #pragma unroll
                for (int j = 0; j < 8; j++)
                    acc[i][j] = fmaf(a[i], b[j], acc[i][j]);
        }
        if (it + 1 < nk) {
            const int nb = buf ^ 1;
            float* as2 = As[nb];
            as2[(ak + 0) * AST + am] = pa.x;
            as2[(ak + 1) * AST + am] = pa.y;
            as2[(ak + 2) * AST + am] = pa.z;
            as2[(ak + 3) * AST + am] = pa.w;
            *(float4*)&Bs[nb][bk * AST + bn] = pb;
        }
        __syncthreads();
    }

    #pragma unroll
    for (int i = 0; i < 8; i++) {
        const int m = m0 + ty * 4 + (i < 4 ? i : 60 + i);
        const float bb = bo[m];
        float4 o0, o1;
        o0.x = acc[i][0] + bb; o0.y = acc[i][1] + bb;
        o0.z = acc[i][2] + bb; o0.w = acc[i][3] + bb;
        o1.x = acc[i][4] + bb; o1.y = acc[i][5] + bb;
        o1.z = acc[i][6] + bb; o1.w = acc[i][7] + bb;
        *(float4*)(z + (long)m * S + ybase * W + tx * 4)      = o0;
        *(float4*)(z + (long)m * S + ybase * W + 64 + tx * 4) = o1;
    }
}

// Wt[m][(dy*3+dx)*256+c] = Wo[((m*256+c)*9 + dy*3+dx]
__global__ void transpose_w(const float* __restrict__ Wo, float* __restrict__ Wt)
{
    int i = blockIdx.x * 256 + threadIdx.x;     // 256*2304
    int m = i / 2304;
    int r = i - m * 2304;
    int dydx = r >> 8;
    int c = r & 255;
    Wt[i] = Wo[((long)m * 256 + c) * 9 + dydx];
}

// ---------------- fallback 64x64x16 GEMM (small shapes) ----------------
template<bool BT>
__global__ __launch_bounds__(256)
void gemm_kernel(const float* __restrict__ A, long sA,
                 const float* __restrict__ Bm, long sB,
                 float* __restrict__ Cm, long sC,
                 const float* __restrict__ bias,
                 int M, int N, int K, float alpha)
{
    const int bz = blockIdx.z;
    A  += bz * sA;
    Bm += bz * sB;
    Cm += bz * sC;
    const int m0 = blockIdx.y * 64;
    const int n0 = blockIdx.x * 64;

    __shared__ float As[16][68];
    __shared__ float Bs[16][68];

    const int tid = threadIdx.x;
    const int tx = tid & 15, ty = tid >> 4;

    float acc[4][4] = {};

    for (int k0 = 0; k0 < K; k0 += 16) {
        {
            int m  = tid >> 2;
            int k4 = (tid & 3) * 4;
            float4 a = *(const float4*)(A + (long)(m0 + m) * K + (k0 + k4));
            As[k4 + 0][m] = a.x; As[k4 + 1][m] = a.y;
            As[k4 + 2][m] = a.z; As[k4 + 3][m] = a.w;
        }
        if (BT) {
            int n  = tid >> 2;
            int k4 = (tid & 3) * 4;
            float4 v = *(const float4*)(Bm + (long)(n0 + n) * K + (k0 + k4));
            Bs[k4 + 0][n] = v.x; Bs[k4 + 1][n] = v.y;
            Bs[k4 + 2][n] = v.z; Bs[k4 + 3][n] = v.w;
        } else {
            int k  = tid >> 4;
            int n4 = (tid & 15) * 4;
            *(float4*)&Bs[k][n4] = *(const float4*)(Bm + (long)(k0 + k) * N + (n0 + n4));
        }
        __syncthreads();

        #pragma unroll
        for (int kk = 0; kk < 16; kk++) {
            float a[4], bv[4];
            *(float4*)a  = *(const float4*)&As[kk][ty * 4];
            *(float4*)bv = *(const float4*)&Bs[kk][tx * 4];
            #pragma unroll
            for (int i = 0; i < 4; i++)
                #pragma unroll
                for (int j = 0; j < 4; j++)
                    acc[i][j] = fmaf(a[i], bv[j], acc[i][j]);
        }
        __syncthreads();
    }

    #pragma unroll
    for (int i = 0; i < 4; i++) {
        int m = m0 + ty * 4 + i;
        float bb = bias ? bias[m] : 0.0f;
        float4 o;
        o.x = acc[i][0] * alpha + bb;
        o.y = acc[i][1] * alpha + bb;
        o.z = acc[i][2] * alpha + bb;
        o.w = acc[i][3] * alpha + bb;
        *(float4*)(Cm + (long)m * N + n0 + tx * 4) = o;
    }
}

// ---------------- token gather / scatter (power-of-2 shifts) ----------------
__global__ void gather_qkv(const float* __restrict__ q, const float* __restrict__ k,
                           const float* __restrict__ v,
                           float* __restrict__ qt, float* __restrict__ kt,
                           float* __restrict__ vt,
                           int base_c, int lp, int louw, int lni, int ldi)
{
    long idx = (long)blockIdx.x * blockDim.x + threadIdx.x;
    int d = (int)(idx & ((1 << ldi) - 1));
    long t = idx >> ldi;
    int n = (int)(t & ((1 << lni) - 1));
    int b = (int)(t >> lni);
    int dc = d >> (2 * lp);
    int r  = d & ((1 << (2 * lp)) - 1);
    int ph = r >> lp, pw = r & ((1 << lp) - 1);
    int oh = n >> louw, ow = n & ((1 << louw) - 1);
    int y = (oh << lp) + ph, x = (ow << lp) + pw;
    long src = ((long)(b * C + base_c + dc)) * S + (long)y * W + x;
    qt[idx] = q[src];
    kt[idx] = k[src];
    vt[idx] = v[src];
}

__global__ void scatter_out(const float* __restrict__ ot, float* __restrict__ att,
                            int base_c, int lp, int louw, int lni, int ldi)
{
    long idx = (long)blockIdx.x * blockDim.x + threadIdx.x;
    int d = (int)(idx & ((1 << ldi) - 1));
    long t = idx >> ldi;
    int n = (int)(t & ((1 << lni) - 1));
    int b = (int)(t >> lni);
    int dc = d >> (2 * lp);
    int r  = d & ((1 << (2 * lp)) - 1);
    int ph = r >> lp, pw = r & ((1 << lp) - 1);
    int oh = n >> louw, ow = n & ((1 << louw) - 1);
    int y = (oh << lp) + ph, x = (ow << lp) + pw;
    long dst = ((long)(b * C + base_c + dc)) * S + (long)y * W + x;
    att[dst] = ot[idx];
}

// ---------------- row softmax ----------------
__global__ void softmax_kernel(float* __restrict__ Smat, int N)
{
    float* r = Smat + (long)blockIdx.x * N;
    __shared__ float red[256];
    int tid = threadIdx.x;

    float m = -1e30f;
    for (int i = tid; i < N; i += 256) m = fmaxf(m, r[i]);
    red[tid] = m; __syncthreads();
    for (int s = 128; s > 0; s >>= 1) {
        if (tid < s) red[tid] = fmaxf(red[tid], red[tid + s]);
        __syncthreads();
    }
    m = red[0];
    __syncthreads();

    float sum = 0.0f;
    for (int i = tid; i < N; i += 256) {
        float e = expf(r[i] - m);
        r[i] = e;
        sum += e;
    }
    red[tid] = sum; __syncthreads();
    for (int s = 128; s > 0; s >>= 1) {
        if (tid < s) red[tid] += red[tid + s];
        __syncthreads();
    }
    float inv = 1.0f / red[0];
    for (int i = tid; i < N; i += 256) r[i] *= inv;
}

// ---------------- batchnorm ----------------
__global__ void bn_stats_kernel(const float* __restrict__ z,
                                float* __restrict__ mean, float* __restrict__ var)
{
    int c = blockIdx.x;
    int tid = threadIdx.x;
    float s = 0.0f, s2 = 0.0f;
    for (int b = 0; b < B; b++) {
        const float* p = z + ((long)(b * C + c)) * S;
        for (int i = tid; i < S; i += 256) {
            float v = p[i];
            s  += v;
            s2 += v * v;
        }
    }
    __shared__ float rs[256], rs2[256];
    rs[tid] = s; rs2[tid] = s2; __syncthreads();
    for (int st = 128; st > 0; st >>= 1) {
        if (tid < st) { rs[tid] += rs[tid + st]; rs2[tid] += rs2[tid + st]; }
        __syncthreads();
    }
    if (tid == 0) {
        float inv = 1.0f / (float)(B * S);
        float m = rs[0] * inv;
        mean[c] = m;
        var[c]  = rs2[0] * inv - m * m;
    }
}

__global__ void bn_apply_kernel(float* __restrict__ z,
                                const float* __restrict__ mean, const float* __restrict__ var,
                                const float* __restrict__ gamma, const float* __restrict__ beta)
{
    long idx = (long)blockIdx.x * 256 + threadIdx.x;
    int c = (int)((idx >> 14) & (C - 1));   // S = 2^14
    float v = z[idx];
    float zn = (v - mean[c]) * rsqrtf(var[c] + 1e-5f);
    zn = zn * gamma[c] + beta[c];
    z[idx] = zn >= 0.0f ? zn : 0.2f * zn;
}

// ---------------- orchestration ----------------
static inline int ilog2(int v) { int l = 0; while ((1 << l) < v) l++; return l; }

extern "C" void kernel_launch(void* const* d_in, const int* in_sizes, int n_in,
                              void* d_out, int out_size)
{
    const float* x     = (const float*)d_in[0];
    const float* y     = (const float*)d_in[1];
    const float* Wq    = (const float*)d_in[2];
    const float* bq    = (const float*)d_in[3];
    const float* Wk    = (const float*)d_in[4];
    const float* bk    = (const float*)d_in[5];
    const float* Wv    = (const float*)d_in[6];
    const float* bv    = (const float*)d_in[7];
    const float* Wo    = (const float*)d_in[8];
    const float* bo    = (const float*)d_in[9];
    const float* gamma = (const float*)d_in[10];
    const float* beta  = (const float*)d_in[11];
    float* out = (float*)d_out;

    float *q, *k, *v, *att, *qt, *kt, *vt, *ot, *sc, *wt, *mean, *var;
    cudaGetSymbolAddress((void**)&q,   g_q);
    cudaGetSymbolAddress((void**)&k,   g_k);
    cudaGetSymbolAddress((void**)&v,   g_v);
    cudaGetSymbolAddress((void**)&att, g_att);
    cudaGetSymbolAddress((void**)&qt,  g_qt);
    cudaGetSymbolAddress((void**)&kt,  g_kt);
    cudaGetSymbolAddress((void**)&vt,  g_vt);
    cudaGetSymbolAddress((void**)&ot,  g_ot);
    cudaGetSymbolAddress((void**)&sc,  g_sc);
    cudaGetSymbolAddress((void**)&wt,  g_wt);
    cudaGetSymbolAddress((void**)&mean, g_mean);
    cudaGetSymbolAddress((void**)&var,  g_var);

    const long bstride = (long)C * S;

    // QKV projections: [256 x 16384] = W[256x256] * in[256x16384] per batch
    dim3 gproj(S / 128, C / 128, B);
    gemm128<false><<<gproj, 256>>>(Wq, 0, x, bstride, q, bstride, bq, C, S, C, 1.0f);
    gemm128<false><<<gproj, 256>>>(Wk, 0, y, bstride, k, bstride, bk, C, S, C, 1.0f);
    gemm128<false><<<gproj, 256>>>(Wv, 0, y, bstride, v, bstride, bv, C, S, C, 1.0f);

    // conv weight transpose (independent of attention; launch early)
    transpose_w<<<(C * C * 9) / 256, 256>>>(Wo, wt);

    const int ps[NSCALE] = {2, 4, 8, 16};
    for (int i = 0; i < NSCALE; i++) {
        int p    = ps[i];
        int outw = W / p;
        int Ni   = outw * outw;
        int Di   = DKC * p * p;
        long tstride = (long)Ni * Di;   // = 1048576
        int lp = ilog2(p), louw = ilog2(outw), lni = ilog2(Ni), ldi = ilog2(Di);
        float alpha = 1.0f / sqrtf((float)Di);

        gather_qkv<<<(B * Ni * Di) / 256, 256>>>(q, k, v, qt, kt, vt,
                                                 i * DKC, lp, louw, lni, ldi);

        // scores = alpha * Qt * Kt^T   [Ni x Ni]
        if (Ni >= 1024) {
            dim3 gs(Ni / 128, Ni / 128, B);
            gemm128<true><<<gs, 256>>>(qt, tstride, kt, tstride, sc, (long)Ni * Ni,
                                       nullptr, Ni, Ni, Di, alpha);
        } else {
            dim3 gs(Ni / 64, Ni / 64, B);
            gemm_kernel<true><<<gs, 256>>>(qt, tstride, kt, tstride, sc, (long)Ni * Ni,
                                           nullptr, Ni, Ni, Di, alpha);
        }

        softmax_kernel<<<B * Ni, 256>>>(sc, Ni);

        // O = P * Vt   [Ni x Di]
        if (Ni >= 128) {
            dim3 gp(Di / 128, Ni / 128, B);
            gemm128<false><<<gp, 256>>>(sc, (long)Ni * Ni, vt, tstride, ot, tstride,
                                        nullptr, Ni, Di, Ni, 1.0f);
        } else {
            dim3 gp(Di / 64, Ni / 64, B);
            gemm_kernel<false><<<gp, 256>>>(sc, (long)Ni * Ni, vt, tstride, ot, tstride,
                                            nullptr, Ni, Di, Ni, 1.0f);
        }

        scatter_out<<<(B * Ni * Di) / 256, 256>>>(ot, att, i * DKC, lp, louw, lni, ldi);
    }

    // conv3x3 as implicit GEMM -> d_out, then BN stats + apply in place
    dim3 gc(S / 128, C / 128, B);     // (128 rows, 2 m-tiles, 4 batches)
    conv_gemm<<<gc, 256>>>(wt, att, bo, out);

    bn_stats_kernel<<<C, 256>>>(out, mean, var);
    bn_apply_kernel<<<((long)B * C * S) / 256, 256>>>(out, mean, var, gamma, beta);
}